// round 1
// baseline (speedup 1.0000x reference)
#include <cuda_runtime.h>
#include <cuda_bf16.h>

#define N_LAYERS 4
#define N_PATCH 196
#define BLK_THREADS 448   // 14 warps: one patch row each
#define IMGS_PER_BLK 32

// 36 precomputed bilinear coefficients: [pair][wire_in_pair][a*3+b],
// basis order (1, cos, sin) for each pixel of the pair.
__device__ float g_coef[36];

// ---------------------------------------------------------------------------
// Setup: fold the entire ansatz (params) into 3x3 bilinear forms.
// Z_j(p0,p1) = sum_{a,b} coef[a][b] * g_a(p0) * g_b(p1),  g = (1, cos p, sin p)
// ---------------------------------------------------------------------------
__global__ void setup_coefs_kernel(const float* __restrict__ params) {
    if (threadIdx.x != 0 || blockIdx.x != 0) return;
    for (int pair = 0; pair < 2; ++pair) {
        float M[4][4] = {{1,0,0,0},{0,1,0,0},{0,0,1,0},{0,0,0,1}};
        for (int l = 0; l < N_LAYERS; ++l) {
            float a = 0.5f * params[l * 4 + 2 * pair];
            float b = 0.5f * params[l * 4 + 2 * pair + 1];
            float ca = cosf(a), sa = sinf(a), cb = cosf(b), sb = sinf(b);
            float Ra[2][2] = {{ca, -sa}, {sa, ca}};
            float Rb[2][2] = {{cb, -sb}, {sb, cb}};
            float R[4][4];
            for (int i = 0; i < 2; i++)
                for (int j = 0; j < 2; j++)
                    for (int k = 0; k < 2; k++)
                        for (int m = 0; m < 2; m++)
                            R[2*i+j][2*k+m] = Ra[i][k] * Rb[j][m];
            float N[4][4];
            for (int r = 0; r < 4; r++)
                for (int c = 0; c < 4; c++) {
                    float s = 0.f;
                    for (int t = 0; t < 4; t++) s += R[r][t] * M[t][c];
                    N[r][c] = s;
                }
            // CX(ctrl=wire0, tgt=wire1): |10> <-> |11>  => swap rows 2,3
            for (int c = 0; c < 4; c++) {
                M[0][c] = N[0][c]; M[1][c] = N[1][c];
                M[2][c] = N[3][c]; M[3][c] = N[2][c];
            }
        }
        // half-angle quadratic -> full-angle basis map
        const float AL[2][2][3] = {
            {{0.5f, 0.5f, 0.f}, {0.f, 0.f, 0.5f}},
            {{0.f, 0.f, 0.5f}, {0.5f, -0.5f, 0.f}}
        };
        for (int jw = 0; jw < 2; ++jw) {
            float Q[4][4];
            for (int r = 0; r < 4; r++)
                for (int c = 0; c < 4; c++) {
                    float s = 0.f;
                    for (int t = 0; t < 4; t++) {
                        float d = (jw == 0) ? ((t < 2) ? 1.f : -1.f)
                                            : ((t & 1) ? -1.f : 1.f);
                        s += d * M[t][r] * M[t][c];
                    }
                    Q[r][c] = s;
                }
            for (int aa = 0; aa < 3; ++aa)
                for (int bb = 0; bb < 3; ++bb) {
                    float s = 0.f;
                    for (int i = 0; i < 2; i++)
                        for (int k = 0; k < 2; k++)
                            for (int j = 0; j < 2; j++)
                                for (int m = 0; m < 2; m++)
                                    s += Q[2*i+j][2*k+m] * AL[i][k][aa] * AL[j][m][bb];
                    g_coef[pair * 18 + jw * 9 + aa * 3 + bb] = s;
                }
        }
    }
}

// ---------------------------------------------------------------------------
// Polynomial sin/cos for p in [0,1):  abs err < 3e-6. No MUFU.
// ---------------------------------------------------------------------------
__device__ __forceinline__ void fsincos01(float p, float& s, float& c) {
    float p2 = p * p;
    s = p * fmaf(p2, fmaf(p2, fmaf(p2, fmaf(p2, 2.7557319e-6f, -1.9841270e-4f),
                                   8.3333333e-3f), -1.6666667e-1f), 1.0f);
    c = fmaf(p2, fmaf(p2, fmaf(p2, fmaf(p2, 2.4801587e-5f, -1.3888889e-3f),
                               4.1666668e-2f), -0.5f), 1.0f);
}

__device__ __forceinline__ float bilin(const float* __restrict__ q,
                                       float Ca, float Sa, float Cb, float Sb) {
    float t0 = fmaf(q[2], Sb, fmaf(q[1], Cb, q[0]));
    float t1 = fmaf(q[5], Sb, fmaf(q[4], Cb, q[3]));
    float t2 = fmaf(q[8], Sb, fmaf(q[7], Cb, q[6]));
    return fmaf(t2, Sa, fmaf(t1, Ca, t0));
}

// ---------------------------------------------------------------------------
// Main: block = 32 images x 14 warps (one patch row each), smem reduce, softmax
// ---------------------------------------------------------------------------
__global__ void __launch_bounds__(BLK_THREADS)
quanv_kernel(const float* __restrict__ x, const float* __restrict__ W,
             const float* __restrict__ bias, float* __restrict__ out) {
    __shared__ float4 Ws[N_PATCH * 10];       // [p*10 + c] = W[c][4p + 0..3]
    __shared__ float red[14][IMGS_PER_BLK][10];
    __shared__ float logit_s[IMGS_PER_BLK][10];
    __shared__ float cf_s[36];

    const int tid = threadIdx.x;
    if (tid < 36) cf_s[tid] = g_coef[tid];
    // W -> smem, reorganized as float4 per (patch, class)
    for (int j = tid; j < N_PATCH * 40; j += BLK_THREADS) {
        int p = j / 40, r = j % 40;
        int c = r >> 2, w = r & 3;
        ((float*)Ws)[j] = W[c * 784 + p * 4 + w];
    }
    __syncthreads();

    float cf[36];
#pragma unroll
    for (int i = 0; i < 36; i++) cf[i] = cf_s[i];

    const int warp = tid >> 5, lane = tid & 31;
    const int img = blockIdx.x * IMGS_PER_BLK + lane;
    const float* xi = x + (long)img * 784;
    const int pr = warp;  // patch row 0..13

    float acc[10];
#pragma unroll
    for (int c = 0; c < 10; c++) acc[c] = 0.f;

#pragma unroll 2
    for (int pc = 0; pc < 14; ++pc) {
        const int p = pr * 14 + pc;
        float2 t = *(const float2*)(xi + pr * 56 + pc * 2);        // pixels w0,w1
        float2 u = *(const float2*)(xi + pr * 56 + 28 + pc * 2);   // pixels w2,w3
        float C0, S0, C1, S1, C2, S2, C3, S3;
        fsincos01(t.x, S0, C0);
        fsincos01(t.y, S1, C1);
        fsincos01(u.x, S2, C2);
        fsincos01(u.y, S3, C3);
        float Z0 = bilin(cf +  0, C0, S0, C1, S1);
        float Z1 = bilin(cf +  9, C0, S0, C1, S1);
        float Z2 = bilin(cf + 18, C2, S2, C3, S3);
        float Z3 = bilin(cf + 27, C2, S2, C3, S3);
        const float4* wp = &Ws[p * 10];
#pragma unroll
        for (int c = 0; c < 10; c++) {
            float4 wv = wp[c];  // broadcast LDS.128 (all lanes same addr)
            acc[c] = fmaf(wv.x, Z0, acc[c]);
            acc[c] = fmaf(wv.y, Z1, acc[c]);
            acc[c] = fmaf(wv.z, Z2, acc[c]);
            acc[c] = fmaf(wv.w, Z3, acc[c]);
        }
    }

#pragma unroll
    for (int c = 0; c < 10; c++) red[warp][lane][c] = acc[c];
    __syncthreads();

    if (tid < IMGS_PER_BLK * 10) {
        int il = tid / 10, c = tid % 10;
        float s = bias[c];
#pragma unroll
        for (int w2 = 0; w2 < 14; w2++) s += red[w2][il][c];
        logit_s[il][c] = s;
    }
    __syncthreads();

    if (tid < IMGS_PER_BLK) {
        float v[10], m = -1e30f;
#pragma unroll
        for (int c = 0; c < 10; c++) { v[c] = logit_s[tid][c]; m = fmaxf(m, v[c]); }
        float se = 0.f;
#pragma unroll
        for (int c = 0; c < 10; c++) se += __expf(v[c] - m);
        float lse = m + __logf(se);
        const long im = (long)blockIdx.x * IMGS_PER_BLK + tid;
#pragma unroll
        for (int c = 0; c < 10; c++) out[im * 10 + c] = v[c] - lse;
    }
}

extern "C" void kernel_launch(void* const* d_in, const int* in_sizes, int n_in,
                              void* d_out, int out_size) {
    const float* x      = (const float*)d_in[0];  // (8192, 784)
    const float* params = (const float*)d_in[1];  // (4, 4)
    const float* W      = (const float*)d_in[2];  // (10, 784)
    const float* bias   = (const float*)d_in[3];  // (10,)
    float* out = (float*)d_out;

    int bsz = in_sizes[0] / 784;
    setup_coefs_kernel<<<1, 1>>>(params);
    quanv_kernel<<<bsz / IMGS_PER_BLK, BLK_THREADS>>>(x, W, bias, out);
}